// round 2
// baseline (speedup 1.0000x reference)
#include <cuda_runtime.h>
#include <math.h>

#define BB 256
#define SS 4096
#define HH 64
#define GG 192   // 3*H

// Scratch: layer activations, in-place across layers, per-batch contiguous.
__device__ float g_buf[(size_t)BB * SS * HH];      // 268 MB
__device__ float g_scores[(size_t)BB * 4 * SS];    // 16 MB

#define FMA_F32X2(d, a, b, c) \
    asm("fma.rn.f32x2 %0, %1, %2, %3;" : "=l"(d) : "l"(a), "l"(b), "l"(c))

__device__ __forceinline__ float2 unpack2_(unsigned long long v) {
    unsigned int lo, hi;
    asm("mov.b64 {%0,%1}, %2;" : "=r"(lo), "=r"(hi) : "l"(v));
    return make_float2(__uint_as_float(lo), __uint_as_float(hi));
}
__device__ __forceinline__ float hsum2_(unsigned long long a, unsigned long long b) {
    float2 pa = unpack2_(a), pb = unpack2_(b);
    return (pa.x + pa.y) + (pb.x + pb.y);
}

__device__ __forceinline__ float sigmoidf_(float x) {
    return __fdividef(1.0f, 1.0f + __expf(-x));
}
__device__ __forceinline__ float tanhf_(float x) {
    x = fminf(fmaxf(x, -15.0f), 15.0f);
    float e = __expf(2.0f * x);
    return __fdividef(e - 1.0f, e + 1.0f);
}

// ---------------------------------------------------------------------------
// GRU layer: one CTA = TWO batch elements, 192 threads = one gate row each.
// Thread j owns row j of W_ih / W_hh in registers (f32x2-packed).
// Phase A: 4 packed dot products (ai,ah for both batches).
// r,z rows (j<128) publish sigmoid pre-gates; barrier.
// Phase B: n rows (j>=128) finish tanh + h update for both batches;
// prefetch threads stage x_{t+1}; barrier.
// ---------------------------------------------------------------------------
template <bool FIRST>
__device__ void gru_layer(
    const float* __restrict__ wih, const float* __restrict__ whh,
    const float* __restrict__ bih, const float* __restrict__ bhh,
    const float* __restrict__ inp0, const float* __restrict__ inp1,
    float* __restrict__ outp0, float* __restrict__ outp1,
    float (*sh)[HH], float (*sx)[2][HH], float (*sxs)[2], float (*srz)[128])
{
    const int j = threadIdx.x;
    constexpr int IN = FIRST ? 1 : HH;

    // ---- weights into registers (packed pairs) ----
    unsigned long long whp[32];
    {
        const ulonglong2* wv = (const ulonglong2*)(whh + j * HH);
#pragma unroll
        for (int kk = 0; kk < 16; kk++) {
            ulonglong2 v = wv[kk];
            whp[2 * kk] = v.x; whp[2 * kk + 1] = v.y;
        }
    }
    unsigned long long wip[FIRST ? 1 : 32];
    float wi0s = 0.0f;
    if (FIRST) {
        wi0s = wih[j];
    } else {
        const ulonglong2* wv = (const ulonglong2*)(wih + j * HH);
#pragma unroll
        for (int kk = 0; kk < 16; kk++) {
            ulonglong2 v = wv[kk];
            wip[2 * kk] = v.x; wip[2 * kk + 1] = v.y;
        }
    }
    const float bi = bih[j];
    const float bh = bhh[j];

    // ---- init h, stage x_0, prefetch x_1 ----
    if (j < HH) { sh[0][j] = 0.0f; sh[1][j] = 0.0f; }
    float xreg = 0.0f;
    const float* myin = nullptr;
    int lane = 0, mb = 0;
    if (j < 2 * IN) {
        mb = (j >= IN) ? 1 : 0;
        lane = j - mb * IN;
        myin = mb ? inp1 : inp0;
        if (FIRST) sxs[0][mb] = myin[lane];
        else       sx[0][mb][lane] = myin[lane];
        xreg = myin[(size_t)IN + lane];
    }
    __syncthreads();

    for (int t = 0; t < SS; t++) {
        const int cur = t & 1;

        // ---- phase A: packed dot products ----
        float ai0, ai1, ah0, ah1;
        {
            const ulonglong2* h0 = (const ulonglong2*)sh[0];
            const ulonglong2* h1 = (const ulonglong2*)sh[1];
            unsigned long long h0a = 0, h0b = 0, h1a = 0, h1b = 0;
            if (FIRST) {
#pragma unroll
                for (int kk = 0; kk < 16; kk++) {
                    ulonglong2 vh0 = h0[kk], vh1 = h1[kk];
                    unsigned long long uA = whp[2 * kk], uB = whp[2 * kk + 1];
                    FMA_F32X2(h0a, uA, vh0.x, h0a); FMA_F32X2(h0b, uB, vh0.y, h0b);
                    FMA_F32X2(h1a, uA, vh1.x, h1a); FMA_F32X2(h1b, uB, vh1.y, h1b);
                }
                ai0 = fmaf(wi0s, sxs[cur][0], bi);
                ai1 = fmaf(wi0s, sxs[cur][1], bi);
            } else {
                const ulonglong2* x0 = (const ulonglong2*)sx[cur][0];
                const ulonglong2* x1 = (const ulonglong2*)sx[cur][1];
                unsigned long long i0a = 0, i0b = 0, i1a = 0, i1b = 0;
#pragma unroll
                for (int kk = 0; kk < 16; kk++) {
                    ulonglong2 vx0 = x0[kk], vx1 = x1[kk];
                    ulonglong2 vh0 = h0[kk], vh1 = h1[kk];
                    unsigned long long wA = wip[2 * kk], wB = wip[2 * kk + 1];
                    unsigned long long uA = whp[2 * kk], uB = whp[2 * kk + 1];
                    FMA_F32X2(i0a, wA, vx0.x, i0a); FMA_F32X2(i0b, wB, vx0.y, i0b);
                    FMA_F32X2(i1a, wA, vx1.x, i1a); FMA_F32X2(i1b, wB, vx1.y, i1b);
                    FMA_F32X2(h0a, uA, vh0.x, h0a); FMA_F32X2(h0b, uB, vh0.y, h0b);
                    FMA_F32X2(h1a, uA, vh1.x, h1a); FMA_F32X2(h1b, uB, vh1.y, h1b);
                }
                ai0 = hsum2_(i0a, i0b) + bi;
                ai1 = hsum2_(i1a, i1b) + bi;
            }
            ah0 = hsum2_(h0a, h0b) + bh;
            ah1 = hsum2_(h1a, h1b) + bh;
        }

        if (j < 128) {
            srz[0][j] = sigmoidf_(ai0 + ah0);
            srz[1][j] = sigmoidf_(ai1 + ah1);
        }
        __syncthreads();

        // ---- phase B ----
        if (j >= 128) {
            const int k = j - 128;
            {
                float r = srz[0][k], z = srz[0][64 + k];
                float n = tanhf_(fmaf(r, ah0, ai0));
                float hn = fmaf(z, sh[0][k] - n, n);
                sh[0][k] = hn;
                outp0[(size_t)t * HH + k] = hn;
            }
            {
                float r = srz[1][k], z = srz[1][64 + k];
                float n = tanhf_(fmaf(r, ah1, ai1));
                float hn = fmaf(z, sh[1][k] - n, n);
                sh[1][k] = hn;
                outp1[(size_t)t * HH + k] = hn;
            }
        } else if (j < 2 * IN) {
            if (FIRST) sxs[1 - cur][mb] = xreg;
            else       sx[1 - cur][mb][lane] = xreg;
            xreg = (t + 2 < SS) ? myin[(size_t)(t + 2) * IN + lane] : 0.0f;
        }
        __syncthreads();
    }
}

__global__ __launch_bounds__(GG)
void gru_kernel(
    const float* __restrict__ x,
    const float* __restrict__ wih0, const float* __restrict__ whh0,
    const float* __restrict__ bih0, const float* __restrict__ bhh0,
    const float* __restrict__ wih1, const float* __restrict__ whh1,
    const float* __restrict__ bih1, const float* __restrict__ bhh1,
    const float* __restrict__ wih2, const float* __restrict__ whh2,
    const float* __restrict__ bih2, const float* __restrict__ bhh2)
{
    __shared__ __align__(16) float sh[2][HH];
    __shared__ __align__(16) float sx[2][2][HH];   // [buf][batch][k]
    __shared__ float sxs[2][2];                    // [buf][batch] for layer 0
    __shared__ float srz[2][128];                  // [batch][row]

    const int b0 = 2 * blockIdx.x;
    const int b1 = b0 + 1;
    float* buf0 = g_buf + (size_t)b0 * SS * HH;
    float* buf1 = g_buf + (size_t)b1 * SS * HH;

    gru_layer<true >(wih0, whh0, bih0, bhh0,
                     x + (size_t)b0 * SS, x + (size_t)b1 * SS,
                     buf0, buf1, sh, sx, sxs, srz);
    __syncthreads();
    gru_layer<false>(wih1, whh1, bih1, bhh1, buf0, buf1, buf0, buf1,
                     sh, sx, sxs, srz);
    __syncthreads();
    gru_layer<false>(wih2, whh2, bih2, bhh2, buf0, buf1, buf0, buf1,
                     sh, sx, sxs, srz);
}

// ---------------------------------------------------------------------------
// Attention + head (unchanged this round).
// ---------------------------------------------------------------------------
__global__ __launch_bounds__(256)
void attn_kernel(
    const float* __restrict__ in_proj_w, const float* __restrict__ in_proj_b,
    const float* __restrict__ out_proj_w, const float* __restrict__ out_proj_b,
    const float* __restrict__ fc_w, const float* __restrict__ fc_b,
    float* __restrict__ out)
{
    const int b = blockIdx.x;
    const int tid = threadIdx.x;

    __shared__ __align__(16) float shl[HH];
    __shared__ __align__(16) float sq[HH];
    __shared__ __align__(16) float sg[4][HH];
    __shared__ float sc[4];
    __shared__ float sred[4][256];
    __shared__ float sm4[4], sl4[4];
    __shared__ __align__(16) float stile[64][HH];   // 16 KB
    __shared__ float sw[4][64];
    __shared__ float su[4][HH];
    __shared__ __align__(16) float sctx[HH];
    __shared__ float sao[HH];

    const float* mybuf = g_buf + (size_t)b * SS * HH;

    if (tid < HH) shl[tid] = mybuf[(size_t)(SS - 1) * HH + tid];
    __syncthreads();

    if (tid < HH) {
        float acc = in_proj_b[tid];
#pragma unroll
        for (int k = 0; k < HH; k++)
            acc = fmaf(in_proj_w[tid * HH + k], shl[k], acc);
        sq[tid] = acc;
    }
    __syncthreads();

    if (tid < HH) {
#pragma unroll
        for (int h = 0; h < 4; h++) {
            float acc = 0.0f;
#pragma unroll
            for (int d = 0; d < 16; d++)
                acc = fmaf(sq[h * 16 + d], in_proj_w[(HH + h * 16 + d) * HH + tid], acc);
            sg[h][tid] = acc * 0.25f;
        }
    }
    if (tid < 4) {
        float acc = 0.0f;
#pragma unroll
        for (int d = 0; d < 16; d++)
            acc = fmaf(sq[tid * 16 + d], in_proj_b[HH + tid * 16 + d], acc);
        sc[tid] = acc * 0.25f;
    }
    __syncthreads();

    float mloc[4] = {-1e30f, -1e30f, -1e30f, -1e30f};
    for (int s = tid; s < SS; s += 256) {
        const float4* ov = (const float4*)(mybuf + (size_t)s * HH);
        float4 o[16];
#pragma unroll
        for (int kk = 0; kk < 16; kk++) o[kk] = ov[kk];
#pragma unroll
        for (int h = 0; h < 4; h++) {
            const float4* gv = (const float4*)sg[h];
            float a0 = sc[h], a1 = 0.f, a2 = 0.f, a3 = 0.f;
#pragma unroll
            for (int kk = 0; kk < 16; kk++) {
                float4 g4 = gv[kk];
                a0 = fmaf(g4.x, o[kk].x, a0);
                a1 = fmaf(g4.y, o[kk].y, a1);
                a2 = fmaf(g4.z, o[kk].z, a2);
                a3 = fmaf(g4.w, o[kk].w, a3);
            }
            float sv = (a0 + a1) + (a2 + a3);
            g_scores[((size_t)(b * 4 + h)) * SS + s] = sv;
            mloc[h] = fmaxf(mloc[h], sv);
        }
    }
#pragma unroll
    for (int h = 0; h < 4; h++) sred[h][tid] = mloc[h];
    __syncthreads();
    if (tid < 4) {
        float m = -1e30f;
        for (int i = 0; i < 256; i++) m = fmaxf(m, sred[tid][i]);
        sm4[tid] = m;
    }
    __syncthreads();

    const int h = tid >> 6;
    const int e = tid & 63;
    const float mh = sm4[h];
    float uacc = 0.0f, lloc = 0.0f;

    for (int tile = 0; tile < SS / 64; tile++) {
        const int s0 = tile * 64;
        {
            float4* st4 = (float4*)stile;
            const float4* gv = (const float4*)(mybuf + (size_t)s0 * HH);
#pragma unroll
            for (int r = 0; r < 4; r++) {
                int idx = tid + r * 256;
                st4[idx] = gv[idx];
            }
        }
        {
            float w = __expf(g_scores[((size_t)(b * 4 + h)) * SS + s0 + e] - mh);
            sw[h][e] = w;
            lloc += w;
        }
        __syncthreads();
#pragma unroll
        for (int sp = 0; sp < 64; sp++)
            uacc = fmaf(sw[h][sp], stile[sp][e], uacc);
        __syncthreads();
    }

    ((float*)sred)[tid] = lloc;
    __syncthreads();
    if (tid < 4) {
        float l = 0.0f;
        for (int i = 0; i < 64; i++) l += ((float*)sred)[tid * 64 + i];
        sl4[tid] = l;
    }
    __syncthreads();

    su[h][e] = uacc / sl4[h];
    __syncthreads();

    if (tid < HH) {
        const int hh = tid >> 4;
        float acc = in_proj_b[128 + tid];
#pragma unroll
        for (int k = 0; k < HH; k++)
            acc = fmaf(in_proj_w[(128 + tid) * HH + k], su[hh][k], acc);
        sctx[tid] = acc;
    }
    __syncthreads();

    if (tid < HH) {
        float acc = out_proj_b[tid];
#pragma unroll
        for (int k = 0; k < HH; k++)
            acc = fmaf(out_proj_w[tid * HH + k], sctx[k], acc);
        sao[tid] = fc_w[tid] * acc;
    }
    __syncthreads();

    if (tid == 0) {
        float lg = fc_b[0];
        for (int i = 0; i < HH; i++) lg += sao[i];
        out[b] = 1.0f / (1.0f + __expf(-lg));
    }
}

// ---------------------------------------------------------------------------
extern "C" void kernel_launch(void* const* d_in, const int* in_sizes, int n_in,
                              void* d_out, int out_size)
{
    const float* x    = (const float*)d_in[0];
    const float* wih0 = (const float*)d_in[1];
    const float* whh0 = (const float*)d_in[2];
    const float* bih0 = (const float*)d_in[3];
    const float* bhh0 = (const float*)d_in[4];
    const float* wih1 = (const float*)d_in[5];
    const float* whh1 = (const float*)d_in[6];
    const float* bih1 = (const float*)d_in[7];
    const float* bhh1 = (const float*)d_in[8];
    const float* wih2 = (const float*)d_in[9];
    const float* whh2 = (const float*)d_in[10];
    const float* bih2 = (const float*)d_in[11];
    const float* bhh2 = (const float*)d_in[12];
    const float* ipw  = (const float*)d_in[13];
    const float* ipb  = (const float*)d_in[14];
    const float* opw  = (const float*)d_in[15];
    const float* opb  = (const float*)d_in[16];
    const float* fcw  = (const float*)d_in[17];
    const float* fcb  = (const float*)d_in[18];

    gru_kernel<<<BB / 2, GG>>>(x, wih0, whh0, bih0, bhh0,
                               wih1, whh1, bih1, bhh1,
                               wih2, whh2, bih2, bhh2);
    attn_kernel<<<BB, 256>>>(ipw, ipb, opw, opb, fcw, fcb, (float*)d_out);
}

// round 4
// speedup vs baseline: 1.1166x; 1.1166x over previous
#include <cuda_runtime.h>
#include <math.h>

#define BB 256
#define SS 4096
#define HH 64
#define GG 192   // 3*H
#define TR 128   // gemm row tile

// Scratch
__device__ float g_buf[(size_t)BB * SS * HH];      // 268 MB  layer activations
__device__ float g_xi [(size_t)BB * SS * GG];      // 805 MB  precomputed input gates
__device__ float g_scores[(size_t)BB * 4 * SS];    // 16 MB

__device__ __forceinline__ float sigmoidf_(float x) {
    return __fdividef(1.0f, 1.0f + __expf(-x));
}
__device__ __forceinline__ float tanhf_(float x) {
    x = fminf(fmaxf(x, -15.0f), 15.0f);
    float e = __expf(2.0f * x);
    return __fdividef(e - 1.0f, e + 1.0f);
}

// dot of 64-reg weight row with smem vector (float4 broadcast reads)
__device__ __forceinline__ float dot64_(const float* __restrict__ w, const float* sv) {
    const float4* hv = (const float4*)sv;
    float a0 = 0.f, a1 = 0.f, a2 = 0.f, a3 = 0.f;
#pragma unroll
    for (int kk = 0; kk < 16; kk++) {
        float4 v = hv[kk];
        a0 = fmaf(w[4 * kk + 0], v.x, a0);
        a1 = fmaf(w[4 * kk + 1], v.y, a1);
        a2 = fmaf(w[4 * kk + 2], v.z, a2);
        a3 = fmaf(w[4 * kk + 3], v.w, a3);
    }
    return (a0 + a1) + (a2 + a3);
}

// ---------------------------------------------------------------------------
// Layer-0 recurrence. One CTA = one batch element, 192 threads = one gate row.
// input_size=1, so xi is computed inline (1 FMA). h-dot from registers vs smem.
// ---------------------------------------------------------------------------
__global__ __launch_bounds__(GG, 2)
void rec0_kernel(const float* __restrict__ x,
                 const float* __restrict__ wih, const float* __restrict__ whh,
                 const float* __restrict__ bih, const float* __restrict__ bhh)
{
    __shared__ __align__(16) float sh[HH];
    __shared__ float sxs[2];
    __shared__ float srz[128];

    const int j = threadIdx.x;
    const int b = blockIdx.x;
    const float* xin = x + (size_t)b * SS;
    float* outp = g_buf + (size_t)b * SS * HH;

    float wh[HH];
#pragma unroll
    for (int k = 0; k < HH; k++) wh[k] = whh[j * HH + k];
    const float wi = wih[j];
    const float bi = bih[j];
    const float bh = bhh[j];

    if (j < HH) sh[j] = 0.0f;
    float xreg = 0.0f;
    if (j == 0) { sxs[0] = xin[0]; xreg = xin[1]; }
    __syncthreads();

    for (int t = 0; t < SS; t++) {
        const int cur = t & 1;
        const float ai = fmaf(wi, sxs[cur], bi);
        const float ah = dot64_(wh, sh) + bh;
        if (j < 128) srz[j] = sigmoidf_(ai + ah);
        __syncthreads();
        if (j >= 128) {
            const int k = j - 128;
            float r = srz[k], z = srz[64 + k];
            float n = tanhf_(fmaf(r, ah, ai));
            float hn = fmaf(z, sh[k] - n, n);
            sh[k] = hn;
            outp[(size_t)t * HH + k] = hn;
        } else if (j == 0) {
            sxs[1 - cur] = xreg;
            xreg = (t + 2 < SS) ? xin[t + 2] : 0.0f;
        }
        __syncthreads();
    }
}

// ---------------------------------------------------------------------------
// xi GEMM: g_xi[row, j] = g_buf[row, :] . wih[j, :] + bih[j]
// rows = B*S. One CTA: 128-row tile, 192 threads (one output col each,
// weight row in registers). A tile staged in smem, broadcast LDS reads.
// ---------------------------------------------------------------------------
__global__ __launch_bounds__(GG)
void xi_gemm_kernel(const float* __restrict__ wih, const float* __restrict__ bih)
{
    __shared__ __align__(16) float sA[TR * HH];   // 32 KB

    const int j = threadIdx.x;
    const size_t row0 = (size_t)blockIdx.x * TR;

    float w[HH];
#pragma unroll
    for (int k = 0; k < HH; k++) w[k] = wih[j * HH + k];
    const float bi = bih[j];

    {
        const float4* src = (const float4*)(g_buf + row0 * HH);
        float4* dst = (float4*)sA;
#pragma unroll
        for (int i = 0; i < (TR * HH / 4) / GG + 1; i++) {
            int idx = j + i * GG;
            if (idx < TR * HH / 4) dst[idx] = src[idx];
        }
    }
    __syncthreads();

    float* outp = g_xi + row0 * GG + j;
#pragma unroll 2
    for (int r = 0; r < TR; r++) {
        float v = dot64_(w, sA + r * HH) + bi;
        outp[(size_t)r * GG] = v;
    }
}

// ---------------------------------------------------------------------------
// Layers 1/2 recurrence: xi precomputed (includes b_ih). Only h-dot per step.
// Each thread's xi element is private -> register double-buffer prefetch.
// ---------------------------------------------------------------------------
__global__ __launch_bounds__(GG, 2)
void rec_kernel(const float* __restrict__ whh, const float* __restrict__ bhh)
{
    __shared__ __align__(16) float sh[HH];
    __shared__ float srz[128];

    const int j = threadIdx.x;
    const int b = blockIdx.x;
    const float* myxi = g_xi + (size_t)b * SS * GG + j;
    float* outp = g_buf + (size_t)b * SS * HH;

    float wh[HH];
#pragma unroll
    for (int k = 0; k < HH; k++) wh[k] = whh[j * HH + k];
    const float bh = bhh[j];

    if (j < HH) sh[j] = 0.0f;
    float xa = myxi[0];
    float xb = myxi[GG];
    __syncthreads();

    for (int t = 0; t < SS; t++) {
        const float ai = xa;
        const float ah = dot64_(wh, sh) + bh;
        if (j < 128) srz[j] = sigmoidf_(ai + ah);
        __syncthreads();
        if (j >= 128) {
            const int k = j - 128;
            float r = srz[k], z = srz[64 + k];
            float n = tanhf_(fmaf(r, ah, ai));
            float hn = fmaf(z, sh[k] - n, n);
            sh[k] = hn;
            outp[(size_t)t * HH + k] = hn;
        }
        xa = xb;
        xb = (t + 2 < SS) ? myxi[(size_t)(t + 2) * GG] : 0.0f;
        __syncthreads();
    }
}

// ---------------------------------------------------------------------------
// Attention + head (unchanged; known-good).
// ---------------------------------------------------------------------------
__global__ __launch_bounds__(256)
void attn_kernel(
    const float* __restrict__ in_proj_w, const float* __restrict__ in_proj_b,
    const float* __restrict__ out_proj_w, const float* __restrict__ out_proj_b,
    const float* __restrict__ fc_w, const float* __restrict__ fc_b,
    float* __restrict__ out)
{
    const int b = blockIdx.x;
    const int tid = threadIdx.x;

    __shared__ __align__(16) float shl[HH];
    __shared__ __align__(16) float sq[HH];
    __shared__ __align__(16) float sg[4][HH];
    __shared__ float sc[4];
    __shared__ float sred[4][256];
    __shared__ float sm4[4], sl4[4];
    __shared__ __align__(16) float stile[64][HH];
    __shared__ float sw[4][64];
    __shared__ float su[4][HH];
    __shared__ __align__(16) float sctx[HH];
    __shared__ float sao[HH];

    const float* mybuf = g_buf + (size_t)b * SS * HH;

    if (tid < HH) shl[tid] = mybuf[(size_t)(SS - 1) * HH + tid];
    __syncthreads();

    if (tid < HH) {
        float acc = in_proj_b[tid];
#pragma unroll
        for (int k = 0; k < HH; k++)
            acc = fmaf(in_proj_w[tid * HH + k], shl[k], acc);
        sq[tid] = acc;
    }
    __syncthreads();

    if (tid < HH) {
#pragma unroll
        for (int h = 0; h < 4; h++) {
            float acc = 0.0f;
#pragma unroll
            for (int d = 0; d < 16; d++)
                acc = fmaf(sq[h * 16 + d], in_proj_w[(HH + h * 16 + d) * HH + tid], acc);
            sg[h][tid] = acc * 0.25f;
        }
    }
    if (tid < 4) {
        float acc = 0.0f;
#pragma unroll
        for (int d = 0; d < 16; d++)
            acc = fmaf(sq[tid * 16 + d], in_proj_b[HH + tid * 16 + d], acc);
        sc[tid] = acc * 0.25f;
    }
    __syncthreads();

    float mloc[4] = {-1e30f, -1e30f, -1e30f, -1e30f};
    for (int s = tid; s < SS; s += 256) {
        const float4* ov = (const float4*)(mybuf + (size_t)s * HH);
        float4 o[16];
#pragma unroll
        for (int kk = 0; kk < 16; kk++) o[kk] = ov[kk];
#pragma unroll
        for (int h = 0; h < 4; h++) {
            const float4* gv = (const float4*)sg[h];
            float a0 = sc[h], a1 = 0.f, a2 = 0.f, a3 = 0.f;
#pragma unroll
            for (int kk = 0; kk < 16; kk++) {
                float4 g4 = gv[kk];
                a0 = fmaf(g4.x, o[kk].x, a0);
                a1 = fmaf(g4.y, o[kk].y, a1);
                a2 = fmaf(g4.z, o[kk].z, a2);
                a3 = fmaf(g4.w, o[kk].w, a3);
            }
            float sv = (a0 + a1) + (a2 + a3);
            g_scores[((size_t)(b * 4 + h)) * SS + s] = sv;
            mloc[h] = fmaxf(mloc[h], sv);
        }
    }
#pragma unroll
    for (int h = 0; h < 4; h++) sred[h][tid] = mloc[h];
    __syncthreads();
    if (tid < 4) {
        float m = -1e30f;
        for (int i = 0; i < 256; i++) m = fmaxf(m, sred[tid][i]);
        sm4[tid] = m;
    }
    __syncthreads();

    const int h = tid >> 6;
    const int e = tid & 63;
    const float mh = sm4[h];
    float uacc = 0.0f, lloc = 0.0f;

    for (int tile = 0; tile < SS / 64; tile++) {
        const int s0 = tile * 64;
        {
            float4* st4 = (float4*)stile;
            const float4* gv = (const float4*)(mybuf + (size_t)s0 * HH);
#pragma unroll
            for (int r = 0; r < 4; r++) {
                int idx = tid + r * 256;
                st4[idx] = gv[idx];
            }
        }
        {
            float w = __expf(g_scores[((size_t)(b * 4 + h)) * SS + s0 + e] - mh);
            sw[h][e] = w;
            lloc += w;
        }
        __syncthreads();
#pragma unroll
        for (int sp = 0; sp < 64; sp++)
            uacc = fmaf(sw[h][sp], stile[sp][e], uacc);
        __syncthreads();
    }

    ((float*)sred)[tid] = lloc;
    __syncthreads();
    if (tid < 4) {
        float l = 0.0f;
        for (int i = 0; i < 64; i++) l += ((float*)sred)[tid * 64 + i];
        sl4[tid] = l;
    }
    __syncthreads();

    su[h][e] = uacc / sl4[h];
    __syncthreads();

    if (tid < HH) {
        const int hh = tid >> 4;
        float acc = in_proj_b[128 + tid];
#pragma unroll
        for (int k = 0; k < HH; k++)
            acc = fmaf(in_proj_w[(128 + tid) * HH + k], su[hh][k], acc);
        sctx[tid] = acc;
    }
    __syncthreads();

    if (tid < HH) {
        float acc = out_proj_b[tid];
#pragma unroll
        for (int k = 0; k < HH; k++)
            acc = fmaf(out_proj_w[tid * HH + k], sctx[k], acc);
        sao[tid] = fc_w[tid] * acc;
    }
    __syncthreads();

    if (tid == 0) {
        float lg = fc_b[0];
        for (int i = 0; i < HH; i++) lg += sao[i];
        out[b] = 1.0f / (1.0f + __expf(-lg));
    }
}

// ---------------------------------------------------------------------------
extern "C" void kernel_launch(void* const* d_in, const int* in_sizes, int n_in,
                              void* d_out, int out_size)
{
    const float* x    = (const float*)d_in[0];
    const float* wih0 = (const float*)d_in[1];
    const float* whh0 = (const float*)d_in[2];
    const float* bih0 = (const float*)d_in[3];
    const float* bhh0 = (const float*)d_in[4];
    const float* wih1 = (const float*)d_in[5];
    const float* whh1 = (const float*)d_in[6];
    const float* bih1 = (const float*)d_in[7];
    const float* bhh1 = (const float*)d_in[8];
    const float* wih2 = (const float*)d_in[9];
    const float* whh2 = (const float*)d_in[10];
    const float* bih2 = (const float*)d_in[11];
    const float* bhh2 = (const float*)d_in[12];
    const float* ipw  = (const float*)d_in[13];
    const float* ipb  = (const float*)d_in[14];
    const float* opw  = (const float*)d_in[15];
    const float* opb  = (const float*)d_in[16];
    const float* fcw  = (const float*)d_in[17];
    const float* fcb  = (const float*)d_in[18];

    const int n_tiles = (BB * SS) / TR;   // 8192

    rec0_kernel<<<BB, GG>>>(x, wih0, whh0, bih0, bhh0);
    xi_gemm_kernel<<<n_tiles, GG>>>(wih1, bih1);
    rec_kernel<<<BB, GG>>>(whh1, bhh1);
    xi_gemm_kernel<<<n_tiles, GG>>>(wih2, bih2);
    rec_kernel<<<BB, GG>>>(whh2, bhh2);
    attn_kernel<<<BB, 256>>>(ipw, ipb, opw, opb, fcw, fcb, (float*)d_out);
}